// round 11
// baseline (speedup 1.0000x reference)
#include <cuda_runtime.h>
#include <math.h>
#include <stdint.h>

#define HH 128
#define WW 128
#define CC 64
#define OO 64
#define BB 4
#define HW (HH*WW)
#define ST 72   // s_A row stride (floats)

// Scratch (no allocations allowed)
__device__ float g_xT[(size_t)BB * HW * CC];   // NHWC x, channels pair-permuted
__device__ float g_wB[9 * 32 * 64 * 2];        // main W: [k][cp][o][pair], tf32
__device__ float g_wOM[9 * 64 * 32];           // off/mod W: [k][pos][n], tf32
__device__ float g_off[(size_t)BB * 18 * HW];  // offsets [b][18][H][W]
__device__ float g_mod[(size_t)BB * HW];       // mod_mean [b][H][W]

// ---------------------------------------------------------------------------
__device__ __forceinline__ float tf32r(float v) {
    uint32_t u;
    asm("cvt.rna.tf32.f32 %0, %1;" : "=r"(u) : "f"(v));
    return __uint_as_float(u);
}

__device__ __forceinline__ void mma8(float* d,
    float a0, float a1, float a2, float a3, float b0, float b1)
{
    asm volatile("mma.sync.aligned.m16n8k8.row.col.f32.tf32.tf32.f32 "
        "{%0,%1,%2,%3}, {%4,%5,%6,%7}, {%8,%9}, {%0,%1,%2,%3};"
        : "+f"(d[0]), "+f"(d[1]), "+f"(d[2]), "+f"(d[3])
        : "r"(__float_as_uint(a0)), "r"(__float_as_uint(a1)),
          "r"(__float_as_uint(a2)), "r"(__float_as_uint(a3)),
          "r"(__float_as_uint(b0)), "r"(__float_as_uint(b1)));
}

// channel permutation: within each 8-group, put (q, q+4) adjacent
__device__ __forceinline__ int cperm(int c) {
    return (c & ~7) + ((c & 3) << 1) + ((c >> 2) & 1);
}

// ---------------------------------------------------------------------------
// K_xtw: [bx<128] NCHW -> NHWC transpose (pair-permuted channels), per (h,b);
//        [bx>=128] weight prep.
// ---------------------------------------------------------------------------
__global__ __launch_bounds__(256) void k_xtw(
    const float* __restrict__ x, const float* __restrict__ w,
    const float* __restrict__ ow, const float* __restrict__ mw)
{
    __shared__ float s[128 * 68];
    int tid = threadIdx.x;

    if (blockIdx.x < 128) {
        int h = blockIdx.x, b = blockIdx.y;
        int lane = tid & 31, wid = tid >> 5;
        const float* xb = x + (size_t)b * CC * HW + h * WW;
#pragma unroll
        for (int wc = 0; wc < 4; wc++) {
            int ww2 = wc * 32 + lane;
#pragma unroll
            for (int cc = 0; cc < 8; cc++) {
                int c = wid * 8 + cc;
                s[ww2 * 68 + cperm(c)] = __ldg(xb + (size_t)c * HW + ww2);
            }
        }
        __syncthreads();
        float4* dst = (float4*)(g_xT + (size_t)(b * HH + h) * WW * CC);
        for (int i = tid; i < 2048; i += 256) {
            int ww2 = i >> 4, c4 = (i & 15) << 2;
            dst[i] = *(float4*)&s[ww2 * 68 + c4];
        }
    } else {
        int idx = ((blockIdx.x - 128) * 4 + blockIdx.y) * 256 + tid;  // 0..55295
        if (idx < 36864) {
            int k = idx >> 12, rem = idx & 4095;
            int cp = rem >> 7, o = (rem >> 1) & 63, j = idx & 1;
            int c = (cp >> 2) * 8 + (cp & 3) + 4 * j;
            g_wB[idx] = tf32r(w[(o * 64 + c) * 9 + k]);
        } else {
            int i2 = idx - 36864;                 // 0..18431
            int k = i2 >> 11, rem = i2 & 2047;
            int pos = rem >> 5, n = rem & 31;
            int c = (pos & ~7) + ((pos & 7) >> 1) + ((pos & 1) << 2);  // inverse cperm
            float v = 0.f;
            if (n < 18)      v = ow[(n * 64 + c) * 9 + k];
            else if (n < 27) v = mw[((n - 18) * 64 + c) * 9 + k];
            g_wOM[i2] = tf32r(v);
        }
    }
}

// ---------------------------------------------------------------------------
// K_offmod: offset/mod conv as GEMM (M128, N32, K576) -> g_off, g_mod.
// LDS.64 A fragments; B staged via clean float4 copy, stride 36 (bank-clean).
// ---------------------------------------------------------------------------
__global__ __launch_bounds__(256) void k_offmod(
    const float* __restrict__ ob_, const float* __restrict__ mb_)
{
    __shared__ float s_A[128 * ST];   // reused as s_out[32][129] after GEMM
    __shared__ float s_W[64 * 36];

    int tid = threadIdx.x, lane = tid & 31, wid = tid >> 5;
    int r = lane >> 2, q = lane & 3;
    int b = blockIdx.z, i0 = blockIdx.y * 16, j0 = blockIdx.x * 8;
    const float* xT = g_xT + (size_t)b * HW * CC;

    float acc1[16];
#pragma unroll
    for (int i = 0; i < 16; i++) acc1[i] = 0.f;
    int m0a = wid * 16;

    for (int k = 0; k < 9; k++) {
        __syncthreads();
        // stage B slice: s_W[pos*36 + n] <- g_wOM[k][pos][n], float4 copy
        {
            const float4* ws = (const float4*)(g_wOM + k * 2048);
#pragma unroll
            for (int i2 = tid; i2 < 512; i2 += 256) {
                int pos = i2 >> 3, n4 = (i2 & 7) << 2;
                *(float4*)&s_W[pos * 36 + n4] = ws[i2];
            }
        }
        int dy = k / 3 - 1, dx = k % 3 - 1;
#pragma unroll 4
        for (int t = 0; t < 16; t++) {
            int p = wid * 16 + t;
            int y = i0 + (p >> 3) + dy;
            int xx = j0 + (p & 7) + dx;
            float2 v = make_float2(0.f, 0.f);
            if ((unsigned)y < HH && (unsigned)xx < WW)
                v = *(const float2*)(xT + ((size_t)y * WW + xx) * CC + 2 * lane);
            v.x = tf32r(v.x); v.y = tf32r(v.y);
            *(float2*)&s_A[p * ST + 2 * lane] = v;
        }
        __syncthreads();

#pragma unroll
        for (int kc = 0; kc < 8; kc++) {
            float2 aA = *(const float2*)&s_A[(m0a + r) * ST + kc * 8 + 2 * q];
            float2 aB = *(const float2*)&s_A[(m0a + 8 + r) * ST + kc * 8 + 2 * q];
            const float* wr0 = s_W + (kc * 8 + 2 * q) * 36 + r;
#pragma unroll
            for (int nt = 0; nt < 4; nt++) {
                float b0 = wr0[nt * 8];
                float b1 = wr0[36 + nt * 8];
                mma8(acc1 + nt * 4, aA.x, aB.x, aA.y, aB.y, b0, b1);
            }
        }
    }
    __syncthreads();
    // stage D -> s_out[n][p] (reuse s_A), stride 129
    {
        float* s_out = s_A;
#pragma unroll
        for (int nt = 0; nt < 4; nt++) {
            int n = nt * 8 + 2 * q;
            s_out[n * 129 + m0a + r]           = acc1[nt * 4 + 0];
            s_out[(n + 1) * 129 + m0a + r]     = acc1[nt * 4 + 1];
            s_out[n * 129 + m0a + r + 8]       = acc1[nt * 4 + 2];
            s_out[(n + 1) * 129 + m0a + r + 8] = acc1[nt * 4 + 3];
        }
    }
    __syncthreads();
    {
        const float* s_out = s_A;
        float* offb = g_off + (size_t)b * 18 * HW;
        for (int i2 = tid; i2 < 18 * 128; i2 += 256) {
            int ch = i2 >> 7, p = i2 & 127;
            offb[ch * HW + (i0 + (p >> 3)) * WW + j0 + (p & 7)] =
                s_out[ch * 129 + p] + __ldg(ob_ + ch);
        }
        if (tid < 128) {
            float s = 0.f;
#pragma unroll
            for (int m2 = 0; m2 < 9; m2++) {
                float vv = s_out[(18 + m2) * 129 + tid] + __ldg(mb_ + m2);
                s += 1.f / (1.f + expf(-vv));
            }
            g_mod[(size_t)b * HW + (i0 + (tid >> 3)) * WW + j0 + (tid & 7)] = s * (1.f / 9.f);
        }
    }
}

// ---------------------------------------------------------------------------
// K_main: precomputed bilinear setup + sampling + GEMM (M128,N64,K576).
// Dynamic smem: s_A[128*72] | s_w4[1152]f4 | s_b4[1152]i4 | s_mod[128]
// ---------------------------------------------------------------------------
#define OFF_A   0
#define OFF_W4  9216
#define OFF_B4  13824
#define OFF_MOD 18432
#define SM_FLOATS 18560
#define SM_BYTES (SM_FLOATS * 4)

__global__ __launch_bounds__(256) void k_main(
    const float* __restrict__ bias, float* __restrict__ out)
{
    extern __shared__ float sm[];
    float*  s_A  = sm + OFF_A;
    float4* s_w4 = (float4*)(sm + OFF_W4);
    int4*   s_b4 = (int4*)(sm + OFF_B4);
    float*  s_mod = sm + OFF_MOD;

    int tid = threadIdx.x, lane = tid & 31, wid = tid >> 5;
    int r = lane >> 2, q = lane & 3;
    int b = blockIdx.z, i0 = blockIdx.y * 16, j0 = blockIdx.x * 8;
    const float* xT = g_xT + (size_t)b * HW * CC;

    // ---- setup phase: 1152 (k,p) bilinear setups distributed over threads ----
    {
        const float* offb = g_off + (size_t)b * 18 * HW;
#pragma unroll
        for (int idx = tid; idx < 1152; idx += 256) {
            int k = idx >> 7, p = idx & 127;
            int py = p >> 3, px = p & 7;
            int pix = (i0 + py) * WW + j0 + px;
            float sy = (float)(i0 + py + (k / 3) - 1) + offb[k * HW + pix];
            float sx = (float)(j0 + px + (k % 3) - 1) + offb[(9 + k) * HW + pix];
            float y0f = floorf(sy), x0f = floorf(sx);
            float wy1 = sy - y0f, wx1 = sx - x0f;
            float wy0 = 1.f - wy1, wx0 = 1.f - wx1;
            int y0 = (int)y0f, x0 = (int)x0f;
            float fy0 = ((unsigned)y0 < HH) ? 1.f : 0.f;
            float fy1 = ((unsigned)(y0 + 1) < HH) ? 1.f : 0.f;
            float fx0 = ((unsigned)x0 < WW) ? 1.f : 0.f;
            float fx1 = ((unsigned)(x0 + 1) < WW) ? 1.f : 0.f;
            int y0c = min(max(y0, 0), HH - 1), y1c = min(max(y0 + 1, 0), HH - 1);
            int x0c = min(max(x0, 0), WW - 1), x1c = min(max(x0 + 1, 0), WW - 1);
            s_w4[idx] = make_float4(wy0 * wx0 * fy0 * fx0, wy0 * wx1 * fy0 * fx1,
                                    wy1 * wx0 * fy1 * fx0, wy1 * wx1 * fy1 * fx1);
            s_b4[idx] = make_int4((y0c * WW + x0c) * CC, (y0c * WW + x1c) * CC,
                                  (y1c * WW + x0c) * CC, (y1c * WW + x1c) * CC);
        }
        if (tid < 128)
            s_mod[tid] = g_mod[(size_t)b * HW + (i0 + (tid >> 3)) * WW + j0 + (tid & 7)];
    }

    float acc[32];
#pragma unroll
    for (int i = 0; i < 32; i++) acc[i] = 0.f;
    int m0 = (wid & 3) * 32, n0 = (wid >> 2) * 32;

    for (int k = 0; k < 9; k++) {
        __syncthreads();   // k=0: setup visible; k>0: GEMM done reading s_A
        const float4* wp = s_w4 + k * 128;
        const int4*   bp = s_b4 + k * 128;
        const float*  xp = xT + 2 * lane;
#pragma unroll 4
        for (int t = 0; t < 16; t++) {
            int p = wid * 16 + t;
            float4 w4 = wp[p];
            int4   b4 = bp[p];
            float2 v00 = *(const float2*)(xp + b4.x);
            float2 v01 = *(const float2*)(xp + b4.y);
            float2 v10 = *(const float2*)(xp + b4.z);
            float2 v11 = *(const float2*)(xp + b4.w);
            float ax = v00.x * w4.x;
            ax = fmaf(v01.x, w4.y, ax);
            ax = fmaf(v10.x, w4.z, ax);
            ax = fmaf(v11.x, w4.w, ax);
            float ay = v00.y * w4.x;
            ay = fmaf(v01.y, w4.y, ay);
            ay = fmaf(v10.y, w4.z, ay);
            ay = fmaf(v11.y, w4.w, ay);
            float2 o2; o2.x = tf32r(ax); o2.y = tf32r(ay);
            *(float2*)&s_A[p * ST + 2 * lane] = o2;
        }
        __syncthreads();

        const float* wb = g_wB + k * 4096 + q * 128 + (n0 + r) * 2;
#pragma unroll
        for (int kc = 0; kc < 8; kc++) {
            float2 aA0 = *(const float2*)&s_A[(m0 + r) * ST + kc * 8 + 2 * q];
            float2 aB0 = *(const float2*)&s_A[(m0 + 8 + r) * ST + kc * 8 + 2 * q];
            float2 aA1 = *(const float2*)&s_A[(m0 + 16 + r) * ST + kc * 8 + 2 * q];
            float2 aB1 = *(const float2*)&s_A[(m0 + 24 + r) * ST + kc * 8 + 2 * q];
#pragma unroll
            for (int nt = 0; nt < 4; nt++) {
                float2 bb = *(const float2*)(wb + kc * 512 + nt * 16);
                mma8(acc + nt * 4,      aA0.x, aB0.x, aA0.y, aB0.y, bb.x, bb.y);
                mma8(acc + 16 + nt * 4, aA1.x, aB1.x, aA1.y, aB1.y, bb.x, bb.y);
            }
        }
    }

    // epilogue: modulate + bias
    {
        float* outb = out + (size_t)b * OO * HW;
#pragma unroll
        for (int mt = 0; mt < 2; mt++) {
#pragma unroll
            for (int half = 0; half < 2; half++) {
                int p = m0 + mt * 16 + r + half * 8;
                float modp = s_mod[p];
                int oy = (i0 + (p >> 3)) * WW + j0 + (p & 7);
#pragma unroll
                for (int nt = 0; nt < 4; nt++) {
                    int o = n0 + nt * 8 + 2 * q;
                    float d0 = acc[mt * 16 + nt * 4 + half * 2 + 0];
                    float d1 = acc[mt * 16 + nt * 4 + half * 2 + 1];
                    outb[(size_t)o * HW + oy]       = fmaf(d0, modp, __ldg(bias + o));
                    outb[(size_t)(o + 1) * HW + oy] = fmaf(d1, modp, __ldg(bias + o + 1));
                }
            }
        }
    }
}

// ---------------------------------------------------------------------------
extern "C" void kernel_launch(void* const* d_in, const int* in_sizes, int n_in,
                              void* d_out, int out_size) {
    const float* x    = (const float*)d_in[0];
    const float* w    = (const float*)d_in[1];
    const float* bias = (const float*)d_in[2];
    const float* ow   = (const float*)d_in[3];
    const float* ob   = (const float*)d_in[4];
    const float* mw   = (const float*)d_in[5];
    const float* mb   = (const float*)d_in[6];
    float* out = (float*)d_out;

    cudaFuncSetAttribute(k_main, cudaFuncAttributeMaxDynamicSharedMemorySize, SM_BYTES);

    k_xtw<<<dim3(182, 4), 256>>>(x, w, ow, mw);
    k_offmod<<<dim3(16, 8, 4), 256>>>(ob, mb);
    k_main<<<dim3(16, 8, 4), 256, SM_BYTES>>>(bias, out);
}

// round 14
// speedup vs baseline: 1.1724x; 1.1724x over previous
#include <cuda_runtime.h>
#include <math.h>
#include <stdint.h>

#define HH 128
#define WW 128
#define CC 64
#define OO 64
#define BB 4
#define HW (HH*WW)
#define ST 72   // s_A row stride (floats): LDS.64 frags -> 2-wavefront floor (verified)

// Scratch (no allocations allowed)
__device__ float g_xT[(size_t)BB * HW * CC];   // NHWC x, channels pair-permuted
__device__ float g_wB[9 * 32 * 64 * 2];        // main W:   [k][cp][o][pair], tf32
__device__ float g_wM[9 * 32 * 32 * 2];        // off/mod W:[k][cp][n][pair], tf32
__device__ float g_off[(size_t)BB * 18 * HW];  // offsets [b][18][H][W]
__device__ float g_mod[(size_t)BB * HW];       // mod_mean [b][H][W]

// ---------------------------------------------------------------------------
__device__ __forceinline__ float tf32r(float v) {
    uint32_t u;
    asm("cvt.rna.tf32.f32 %0, %1;" : "=r"(u) : "f"(v));
    return __uint_as_float(u);
}

__device__ __forceinline__ void mma8(float* d,
    float a0, float a1, float a2, float a3, float b0, float b1)
{
    asm volatile("mma.sync.aligned.m16n8k8.row.col.f32.tf32.tf32.f32 "
        "{%0,%1,%2,%3}, {%4,%5,%6,%7}, {%8,%9}, {%0,%1,%2,%3};"
        : "+f"(d[0]), "+f"(d[1]), "+f"(d[2]), "+f"(d[3])
        : "r"(__float_as_uint(a0)), "r"(__float_as_uint(a1)),
          "r"(__float_as_uint(a2)), "r"(__float_as_uint(a3)),
          "r"(__float_as_uint(b0)), "r"(__float_as_uint(b1)));
}

// channel permutation: within each 8-group, put (q, q+4) adjacent
__device__ __forceinline__ int cperm(int c) {
    return (c & ~7) + ((c & 3) << 1) + ((c >> 2) & 1);
}

// ---------------------------------------------------------------------------
// K_xtw: [bx<128] NCHW -> NHWC transpose (pair-permuted channels), per (h,b);
//        [bx>=128] weight prep (pair-packed, tf32-rounded): g_wB, g_wM.
// ---------------------------------------------------------------------------
__global__ __launch_bounds__(256) void k_xtw(
    const float* __restrict__ x, const float* __restrict__ w,
    const float* __restrict__ ow, const float* __restrict__ mw)
{
    __shared__ float s[128 * 68];
    int tid = threadIdx.x;

    if (blockIdx.x < 128) {
        int h = blockIdx.x, b = blockIdx.y;
        int lane = tid & 31, wid = tid >> 5;
        const float* xb = x + (size_t)b * CC * HW + h * WW;
#pragma unroll
        for (int wc = 0; wc < 4; wc++) {
            int ww2 = wc * 32 + lane;
#pragma unroll
            for (int cc = 0; cc < 8; cc++) {
                int c = wid * 8 + cc;
                s[ww2 * 68 + cperm(c)] = __ldg(xb + (size_t)c * HW + ww2);
            }
        }
        __syncthreads();
        float4* dst = (float4*)(g_xT + (size_t)(b * HH + h) * WW * CC);
        for (int i = tid; i < 2048; i += 256) {
            int ww2 = i >> 4, c4 = (i & 15) << 2;
            dst[i] = *(float4*)&s[ww2 * 68 + c4];
        }
    } else {
        int idx = ((blockIdx.x - 128) * 4 + blockIdx.y) * 256 + tid;  // 0..55295
        if (idx < 36864) {
            int k = idx >> 12, rem = idx & 4095;
            int cp = rem >> 7, o = (rem >> 1) & 63, j = idx & 1;
            int c = (cp >> 2) * 8 + (cp & 3) + 4 * j;
            g_wB[idx] = tf32r(w[(o * 64 + c) * 9 + k]);
        } else {
            int i2 = idx - 36864;                 // 0..18431
            int k = i2 >> 11, rem = i2 & 2047;
            int cp = rem >> 6, n = (rem >> 1) & 31, j = i2 & 1;
            int c = (cp >> 2) * 8 + (cp & 3) + 4 * j;
            float v = 0.f;
            if (n < 18)      v = ow[(n * 64 + c) * 9 + k];
            else if (n < 27) v = mw[((n - 18) * 64 + c) * 9 + k];
            g_wM[i2] = tf32r(v);
        }
    }
}

// ---------------------------------------------------------------------------
// K_offmod: offset/mod conv as GEMM (M128, N32, K576) -> g_off, g_mod.
// A: LDS.64 frags stride 72 (conflict-free). B: staged to s_W stride 72,
// float2 frags at (kc*4+q)*72 + 2r (+16nt) -> per-phase banks 4q+r distinct.
// ---------------------------------------------------------------------------
__global__ __launch_bounds__(256) void k_offmod(
    const float* __restrict__ ob_, const float* __restrict__ mb_)
{
    __shared__ float s_A[128 * ST];   // reused as s_out[32][129] after GEMM
    __shared__ float s_W[32 * 72];    // [cp][n][pair] padded

    int tid = threadIdx.x, lane = tid & 31, wid = tid >> 5;
    int r = lane >> 2, q = lane & 3;
    int b = blockIdx.z, i0 = blockIdx.y * 16, j0 = blockIdx.x * 8;
    const float* xT = g_xT + (size_t)b * HW * CC;

    float acc1[16];
#pragma unroll
    for (int i = 0; i < 16; i++) acc1[i] = 0.f;
    int m0a = wid * 16;

    for (int k = 0; k < 9; k++) {
        __syncthreads();
        // stage B slice: 512 float4 copies, s_W[cp*72 + rem*4]
        {
            const float4* ws = (const float4*)(g_wM + k * 2048);
            for (int i2 = tid; i2 < 512; i2 += 256) {
                int cp = i2 >> 4, rem = i2 & 15;
                *(float4*)&s_W[cp * 72 + rem * 4] = ws[i2];
            }
        }
        int dy = k / 3 - 1, dx = k % 3 - 1;
#pragma unroll 4
        for (int t = 0; t < 16; t++) {
            int p = wid * 16 + t;
            int y = i0 + (p >> 3) + dy;
            int xx = j0 + (p & 7) + dx;
            float2 v = make_float2(0.f, 0.f);
            if ((unsigned)y < HH && (unsigned)xx < WW)
                v = *(const float2*)(xT + ((size_t)y * WW + xx) * CC + 2 * lane);
            v.x = tf32r(v.x); v.y = tf32r(v.y);
            *(float2*)&s_A[p * ST + 2 * lane] = v;
        }
        __syncthreads();

#pragma unroll
        for (int kc = 0; kc < 8; kc++) {
            float2 aA = *(const float2*)&s_A[(m0a + r) * ST + kc * 8 + 2 * q];
            float2 aB = *(const float2*)&s_A[(m0a + 8 + r) * ST + kc * 8 + 2 * q];
            const float* wr0 = s_W + (kc * 4 + q) * 72 + 2 * r;
#pragma unroll
            for (int nt = 0; nt < 4; nt++) {
                float2 bb = *(const float2*)(wr0 + 16 * nt);
                mma8(acc1 + nt * 4, aA.x, aB.x, aA.y, aB.y, bb.x, bb.y);
            }
        }
    }
    __syncthreads();
    // stage D -> s_out[n][p] (reuse s_A), stride 129
    {
        float* s_out = s_A;
#pragma unroll
        for (int nt = 0; nt < 4; nt++) {
            int n = nt * 8 + 2 * q;
            s_out[n * 129 + m0a + r]           = acc1[nt * 4 + 0];
            s_out[(n + 1) * 129 + m0a + r]     = acc1[nt * 4 + 1];
            s_out[n * 129 + m0a + r + 8]       = acc1[nt * 4 + 2];
            s_out[(n + 1) * 129 + m0a + r + 8] = acc1[nt * 4 + 3];
        }
    }
    __syncthreads();
    {
        const float* s_out = s_A;
        float* offb = g_off + (size_t)b * 18 * HW;
        for (int i2 = tid; i2 < 18 * 128; i2 += 256) {
            int ch = i2 >> 7, p = i2 & 127;
            offb[ch * HW + (i0 + (p >> 3)) * WW + j0 + (p & 7)] =
                s_out[ch * 129 + p] + __ldg(ob_ + ch);
        }
        if (tid < 128) {
            float s = 0.f;
#pragma unroll
            for (int m2 = 0; m2 < 9; m2++) {
                float vv = s_out[(18 + m2) * 129 + tid] + __ldg(mb_ + m2);
                s += 1.f / (1.f + expf(-vv));
            }
            g_mod[(size_t)b * HW + (i0 + (tid >> 3)) * WW + j0 + (tid & 7)] = s * (1.f / 9.f);
        }
    }
}

// ---------------------------------------------------------------------------
// K_main: bilinear sampling + main GEMM (M128, N64, K576) + epilogue.
// Exact R8 version (measured 108.7us): LDS.64 A frags, B via LDG.64 from g_wB.
// ---------------------------------------------------------------------------
__global__ __launch_bounds__(256) void k_main(
    const float* __restrict__ bias, float* __restrict__ out)
{
    __shared__ float s_A[128 * ST];
    __shared__ float s_off[18 * 128];
    __shared__ float s_mod[128];

    int tid = threadIdx.x, lane = tid & 31, wid = tid >> 5;
    int r = lane >> 2, q = lane & 3;
    int b = blockIdx.z, i0 = blockIdx.y * 16, j0 = blockIdx.x * 8;
    const float* xT = g_xT + (size_t)b * HW * CC;

    const float* offb = g_off + (size_t)b * 18 * HW;
    for (int i2 = tid; i2 < 18 * 128; i2 += 256) {
        int ch = i2 >> 7, p = i2 & 127;
        s_off[i2] = offb[ch * HW + (i0 + (p >> 3)) * WW + j0 + (p & 7)];
    }
    if (tid < 128)
        s_mod[tid] = g_mod[(size_t)b * HW + (i0 + (tid >> 3)) * WW + j0 + (tid & 7)];

    float acc[32];
#pragma unroll
    for (int i = 0; i < 32; i++) acc[i] = 0.f;
    int m0 = (wid & 3) * 32, n0 = (wid >> 2) * 32;

    for (int k = 0; k < 9; k++) {
        __syncthreads();
        float fdy = (float)(k / 3 - 1), fdx = (float)(k % 3 - 1);
#pragma unroll 2
        for (int t = 0; t < 16; t++) {
            int p = wid * 16 + t;
            float sy = (float)(i0 + (p >> 3)) + fdy + s_off[k * 128 + p];
            float sx = (float)(j0 + (p & 7)) + fdx + s_off[(9 + k) * 128 + p];
            float y0f = floorf(sy), x0f = floorf(sx);
            float wy1 = sy - y0f, wx1 = sx - x0f;
            float wy0 = 1.f - wy1, wx0 = 1.f - wx1;
            int y0 = (int)y0f, x0 = (int)x0f;
            bool yi0 = (unsigned)y0 < HH;
            bool yi1 = (unsigned)(y0 + 1) < HH;
            bool xi0 = (unsigned)x0 < WW;
            bool xi1 = (unsigned)(x0 + 1) < WW;
            const float* base = xT + ((size_t)y0 * WW + x0) * CC + 2 * lane;
            float ax = 0.f, ay = 0.f;
            if (yi0 && xi0) { float2 v = *(const float2*)(base);
                float w00 = wy0 * wx0; ax = fmaf(w00, v.x, ax); ay = fmaf(w00, v.y, ay); }
            if (yi0 && xi1) { float2 v = *(const float2*)(base + CC);
                float w01 = wy0 * wx1; ax = fmaf(w01, v.x, ax); ay = fmaf(w01, v.y, ay); }
            if (yi1 && xi0) { float2 v = *(const float2*)(base + WW * CC);
                float w10 = wy1 * wx0; ax = fmaf(w10, v.x, ax); ay = fmaf(w10, v.y, ay); }
            if (yi1 && xi1) { float2 v = *(const float2*)(base + WW * CC + CC);
                float w11 = wy1 * wx1; ax = fmaf(w11, v.x, ax); ay = fmaf(w11, v.y, ay); }
            float2 o2; o2.x = tf32r(ax); o2.y = tf32r(ay);
            *(float2*)&s_A[p * ST + 2 * lane] = o2;
        }
        __syncthreads();

        const float* wb = g_wB + k * 4096 + q * 128 + (n0 + r) * 2;
#pragma unroll
        for (int kc = 0; kc < 8; kc++) {
            float2 aA0 = *(const float2*)&s_A[(m0 + r) * ST + kc * 8 + 2 * q];
            float2 aB0 = *(const float2*)&s_A[(m0 + 8 + r) * ST + kc * 8 + 2 * q];
            float2 aA1 = *(const float2*)&s_A[(m0 + 16 + r) * ST + kc * 8 + 2 * q];
            float2 aB1 = *(const float2*)&s_A[(m0 + 24 + r) * ST + kc * 8 + 2 * q];
#pragma unroll
            for (int nt = 0; nt < 4; nt++) {
                float2 bb = *(const float2*)(wb + kc * 512 + nt * 16);
                mma8(acc + nt * 4,      aA0.x, aB0.x, aA0.y, aB0.y, bb.x, bb.y);
                mma8(acc + 16 + nt * 4, aA1.x, aB1.x, aA1.y, aB1.y, bb.x, bb.y);
            }
        }
    }

    // epilogue: modulate + bias
    {
        float* outb = out + (size_t)b * OO * HW;
#pragma unroll
        for (int mt = 0; mt < 2; mt++) {
#pragma unroll
            for (int half = 0; half < 2; half++) {
                int p = m0 + mt * 16 + r + half * 8;
                float modp = s_mod[p];
                int oy = (i0 + (p >> 3)) * WW + j0 + (p & 7);
#pragma unroll
                for (int nt = 0; nt < 4; nt++) {
                    int o = n0 + nt * 8 + 2 * q;
                    float d0 = acc[mt * 16 + nt * 4 + half * 2 + 0];
                    float d1 = acc[mt * 16 + nt * 4 + half * 2 + 1];
                    outb[(size_t)o * HW + oy]       = fmaf(d0, modp, __ldg(bias + o));
                    outb[(size_t)(o + 1) * HW + oy] = fmaf(d1, modp, __ldg(bias + o + 1));
                }
            }
        }
    }
}

// ---------------------------------------------------------------------------
extern "C" void kernel_launch(void* const* d_in, const int* in_sizes, int n_in,
                              void* d_out, int out_size) {
    const float* x    = (const float*)d_in[0];
    const float* w    = (const float*)d_in[1];
    const float* bias = (const float*)d_in[2];
    const float* ow   = (const float*)d_in[3];
    const float* ob   = (const float*)d_in[4];
    const float* mw   = (const float*)d_in[5];
    const float* mb   = (const float*)d_in[6];
    float* out = (float*)d_out;

    k_xtw<<<dim3(182, 4), 256>>>(x, w, ow, mw);
    k_offmod<<<dim3(16, 8, 4), 256>>>(ob, mb);
    k_main<<<dim3(16, 8, 4), 256>>>(bias, out);
}